// round 15
// baseline (speedup 1.0000x reference)
#include <cuda_runtime.h>
#include <cuda_fp16.h>
#include <cstdint>
#include <cstddef>

// ---------------- problem constants ----------------
#define V_SIZE 1024
#define H_SIZE 2048
#define F_SIZE 3072
#define T_STEPS 64
#define REC_F 0.8f

// ---------------- GEMM tiling (dual-CTA-per-SM + loader warp) ----------------
#define BM 128
#define BN 96
#define BK 64
#define KCHUNKS (F_SIZE / BK)   // 48
#define NTHREADS 160            // warps 0-3 compute (2M x 2N, 64x48), warp 4 loads
#define NSTAGES 2

// SMEM per stage: A(16K) Bh(12K) Bl(12K) = 40K
#define OFF_A  0
#define OFF_BH 16384
#define OFF_BL 28672
#define STAGE_BYTES 40960
// layout: [align slack 1K][hdr 1K: mbarriers][2 stages] = 84KB -> 2 CTAs/SM
#define SMEM_BYTES (1024 + 1024 + NSTAGES * STAGE_BYTES)

// ---------------- device scratch ----------------
// Wh = fp16(W); Wl = fp16((W - Wh) * 64)  (scaled into fp16-normal range)
__device__ __half g_Wh[(size_t)F_SIZE * F_SIZE];
__device__ __half g_Wl[(size_t)F_SIZE * F_SIZE];
__device__ __half g_R[2][(size_t)V_SIZE * F_SIZE];

__device__ __forceinline__ uint32_t swz(uint32_t o) { return o ^ ((o >> 3) & 0x70u); }

#define LDM4(R_, A_)                                                              \
  asm volatile("ldmatrix.sync.aligned.m8n8.x4.shared.b16 {%0,%1,%2,%3}, [%4];"    \
               : "=r"((R_)[0]), "=r"((R_)[1]), "=r"((R_)[2]), "=r"((R_)[3])       \
               : "r"(A_))

#define MMA16816(C_, A_, B0_, B1_)                                                \
  asm volatile("mma.sync.aligned.m16n8k16.row.col.f32.f16.f16.f32 "               \
               "{%0,%1,%2,%3},{%4,%5,%6,%7},{%8,%9},{%0,%1,%2,%3};"               \
               : "+f"((C_)[0]), "+f"((C_)[1]), "+f"((C_)[2]), "+f"((C_)[3])       \
               : "r"((A_)[0]), "r"((A_)[1]), "r"((A_)[2]), "r"((A_)[3]),          \
                 "r"(B0_), "r"(B1_))

#define CP16(SO_, G_)                                                             \
  asm volatile("cp.async.cg.shared.global [%0], [%1], 16;" :: "r"(SO_), "l"(G_))

// .noinc: one arrival per thread when that thread's prior cp.asyncs complete.
#define CP_ASYNC_MBAR_ARRIVE_NOINC(mbar)                                          \
  asm volatile("cp.async.mbarrier.arrive.noinc.shared.b64 [%0];"                  \
               :: "r"((uint32_t)(mbar)) : "memory")

#define MBARRIER_INIT(mbar, count)                                                \
  asm volatile("mbarrier.init.shared.b64 [%0], %1;"                               \
               :: "r"((uint32_t)(mbar)), "r"((uint32_t)(count)) : "memory")
#define MBARRIER_ARRIVE(mbar)                                                     \
  asm volatile("mbarrier.arrive.shared.b64 _, [%0];"                              \
               :: "r"((uint32_t)(mbar)) : "memory")

// acquire wait (consumers: post-wait LDSM reads need ordering)
__device__ __forceinline__ void mbar_wait_parity(uint32_t mbar, uint32_t parity) {
  uint32_t done;
  asm volatile("{\n\t.reg .pred p;\n\t"
               "mbarrier.try_wait.parity.acquire.cta.shared::cta.b64 p, [%1], %2;\n\t"
               "selp.b32 %0, 1, 0, p;\n\t}"
               : "=r"(done) : "r"(mbar), "r"(parity) : "memory");
  if (!done) {
    asm volatile("{\n\t.reg .pred P1;\n\t"
                 "WAIT_LOOP_%=:\n\t"
                 "mbarrier.try_wait.parity.acquire.cta.shared::cta.b64 P1, [%0], %1, 0x989680;\n\t"
                 "@P1 bra.uni WAIT_DONE_%=;\n\t"
                 "bra.uni WAIT_LOOP_%=;\n\t"
                 "WAIT_DONE_%=:\n\t}"
                 :: "r"(mbar), "r"(parity) : "memory");
  }
}

// relaxed wait (producer: post-wait accesses are cp.async = async proxy)
__device__ __forceinline__ void mbar_wait_parity_relaxed(uint32_t mbar,
                                                         uint32_t parity) {
  uint32_t done;
  asm volatile("{\n\t.reg .pred p;\n\t"
               "mbarrier.try_wait.parity.relaxed.cta.shared::cta.b64 p, [%1], %2;\n\t"
               "selp.b32 %0, 1, 0, p;\n\t}"
               : "=r"(done) : "r"(mbar), "r"(parity) : "memory");
  if (!done) {
    asm volatile("{\n\t.reg .pred P1;\n\t"
                 "WAIT_LOOP_%=:\n\t"
                 "mbarrier.try_wait.parity.relaxed.cta.shared::cta.b64 P1, [%0], %1, 0x989680;\n\t"
                 "@P1 bra.uni WAIT_DONE_%=;\n\t"
                 "bra.uni WAIT_LOOP_%=;\n\t"
                 "WAIT_DONE_%=:\n\t}"
                 :: "r"(mbar), "r"(parity) : "memory");
  }
}

#define HALF2_POW2_M6 0x24002400u
__device__ __forceinline__ uint32_t hmul2_scale(uint32_t a) {
  uint32_t r;
  asm volatile("mul.f16x2 %0, %1, %2;" : "=r"(r) : "r"(a), "r"(HALF2_POW2_M6));
  return r;
}

__device__ __forceinline__ float fast_tanh(float x) {
  float e = __expf(2.f * x);
  return 1.f - __fdividef(2.f, e + 1.f);
}

// -------- W split: fp32 -> fp16 hi + fp16 lo (lo pre-scaled by 2^6) --------
__global__ void split_w_kernel(const float* __restrict__ W) {
  const int n = F_SIZE * F_SIZE;
  for (int i = blockIdx.x * blockDim.x + threadIdx.x; i < n;
       i += gridDim.x * blockDim.x) {
    float w = W[i];
    __half h = __float2half(w);
    g_Wh[i] = h;
    g_Wl[i] = __float2half((w - __half2float(h)) * 64.f);
  }
}

// -------- step 0: R_0 = 0, epilogue-only --------
__global__ void step0_kernel(const float* __restrict__ X,
                             const float* __restrict__ b,
                             const float* __restrict__ lam) {
  const int n = V_SIZE * F_SIZE;
  for (int i = blockIdx.x * blockDim.x + threadIdx.x; i < n;
       i += gridDim.x * blockDim.x) {
    int c = i % F_SIZE;
    float l = lam[i];
    float u = l * b[c];
    if (c < V_SIZE) u += (1.f - l) * X[c];  // x_0
    g_R[1][i] = __float2half(tanhf(u));
  }
}

// -------- steps 1..62: warp-specialized fp16 2-pass GEMM + fused epilogue ----
__global__ void __launch_bounds__(NTHREADS, 2)
gemm_step_kernel(int t, const float* __restrict__ X, const float* __restrict__ b) {
  extern __shared__ unsigned char smem_raw[];
  uint32_t sbase = (uint32_t)__cvta_generic_to_shared(smem_raw);
  sbase = (sbase + 1023u) & ~1023u;
  const uint32_t hdr = sbase;        // full[s]=hdr+s*8, empty[s]=hdr+64+s*8
  const uint32_t tiles = sbase + 1024;

  const __half* __restrict__ A = g_R[t & 1];
  __half* __restrict__ O = g_R[(t + 1) & 1];
  const float* __restrict__ Xr = X + (size_t)t * V_SIZE;

  const int tid = threadIdx.x;
  const int lane = tid & 31;
  const int wid = tid >> 5;
  const int m0 = blockIdx.y * BM;
  const int n0 = blockIdx.x * BN;

  const __half* __restrict__ srcA  = A + (size_t)m0 * F_SIZE;
  const __half* __restrict__ srcBh = g_Wh + (size_t)n0 * F_SIZE;
  const __half* __restrict__ srcBl = g_Wl + (size_t)n0 * F_SIZE;

  // full[s]: 32 loader-thread arrivals; empty[s]: 128 compute-thread arrivals
  if (tid == 0) {
#pragma unroll
    for (int s = 0; s < NSTAGES; ++s) {
      MBARRIER_INIT(hdr + s * 8, 32);
      MBARRIER_INIT(hdr + 64 + s * 8, 128);
    }
  }
  __syncthreads();

  if (wid == 4) {
    // ================= loader warp =================
    auto load_chunk = [&](int stage, int kc) {
      const uint32_t sb = tiles + (uint32_t)stage * STAGE_BYTES;
      const int koff = kc * BK;
      // 2560 16B items: A rows 0-127 (1024), Bh (768), Bl (768); 80 per lane
#pragma unroll 8
      for (int it = 0; it < 80; ++it) {
        int i = lane + it * 32;
        const __half* gb;
        uint32_t stile;
        int j;
        if (i < 1024)      { j = i;        gb = srcA;  stile = OFF_A;  }
        else if (i < 1792) { j = i - 1024; gb = srcBh; stile = OFF_BH; }
        else               { j = i - 1792; gb = srcBl; stile = OFF_BL; }
        int r = j >> 3, c = j & 7;
        const void* g = gb + (size_t)r * F_SIZE + koff + c * 8;
        uint32_t so = sb + stile + swz((uint32_t)(r * 128 + c * 16));
        CP16(so, g);
      }
      CP_ASYNC_MBAR_ARRIVE_NOINC(hdr + stage * 8);  // full[stage]
    };

    load_chunk(0, 0);
    load_chunk(1, 1);
    for (int kc = 0; kc + 2 < KCHUNKS; ++kc) {
      const int s = kc & 1;
      // wait: all compute warps finished reading chunk kc from stage s
      mbar_wait_parity_relaxed(hdr + 64 + s * 8, (uint32_t)((kc >> 1) & 1));
      load_chunk(s, kc + 2);
    }
    return;  // loader warp done (no epilogue tile)
  }

  // ================= compute warps (0-3) =================
  const int wm = (wid >> 1) * 64;      // 0 / 64
  const int wn = (wid & 1) * 48;       // 0 / 48

  float acc[4][6][4];
#pragma unroll
  for (int i = 0; i < 4; ++i)
#pragma unroll
    for (int j = 0; j < 6; ++j)
#pragma unroll
      for (int k = 0; k < 4; ++k) acc[i][j][k] = 0.f;

  auto compute = [&](int stage) {
    const uint32_t sb = tiles + (uint32_t)stage * STAGE_BYTES;
    const uint32_t aT = sb + OFF_A;
    const uint32_t bH = sb + OFF_BH;
    const uint32_t bL = sb + OFF_BL;
#pragma unroll
    for (int ks = 0; ks < 4; ++ks) {
      uint32_t ah[4][4], as[4][4], bh[3][4], bl[3][4];
#pragma unroll
      for (int mf = 0; mf < 4; ++mf) {
        uint32_t off = swz((uint32_t)((wm + mf * 16 + (lane & 15)) * 128 +
                                      (ks * 16 + ((lane >> 4) << 3)) * 2));
        LDM4(ah[mf], aT + off);
#pragma unroll
        for (int q = 0; q < 4; ++q) as[mf][q] = hmul2_scale(ah[mf][q]);
      }
#pragma unroll
      for (int nf2 = 0; nf2 < 3; ++nf2) {
        uint32_t off = swz((uint32_t)(
            (wn + nf2 * 16 + (lane & 7) + (((lane >> 4) & 1) << 3)) * 128 +
            (ks * 16 + ((lane >> 3) & 1) * 8) * 2));
        LDM4(bh[nf2], bH + off);
        LDM4(bl[nf2], bL + off);
      }
      if (ks == 3) {
        // this thread's reads from `stage` done (fragments in regs)
        MBARRIER_ARRIVE(hdr + 64 + stage * 8);  // empty[stage]
      }
#pragma unroll
      for (int mf = 0; mf < 4; ++mf)
#pragma unroll
        for (int nf = 0; nf < 6; ++nf) {
          float* c = acc[mf][nf];
          uint32_t b0h = bh[nf >> 1][(nf & 1) * 2];
          uint32_t b1h = bh[nf >> 1][(nf & 1) * 2 + 1];
          uint32_t b0l = bl[nf >> 1][(nf & 1) * 2];
          uint32_t b1l = bl[nf >> 1][(nf & 1) * 2 + 1];
          MMA16816(c, ah[mf], b0h, b1h);  // Rh * Wh
          MMA16816(c, as[mf], b0l, b1l);  // (Rh*2^-6) * (Wl*2^6) = Rh * Wl
        }
    }
  };

  // mainloop: only one TRYWAIT per chunk on the compute critical path
  for (int kc = 0; kc < KCHUNKS; ++kc) {
    const int s = kc & 1;
    mbar_wait_parity(hdr + s * 8, (uint32_t)((kc >> 1) & 1));  // full[s]
    compute(s);  // empty-arrive inside (ks==3)
  }

  // --- fused epilogue: lam from indices; U = lam*(C+b) + (1-lam)*x_t; tanh ---
#pragma unroll
  for (int mf = 0; mf < 4; ++mf)
#pragma unroll
    for (int nf = 0; nf < 6; ++nf)
#pragma unroll
      for (int half = 0; half < 2; ++half) {
        int m = m0 + wm + mf * 16 + (lane >> 2) + half * 8;
        int n = n0 + wn + nf * 8 + 2 * (lane & 3);
        size_t idx = (size_t)m * F_SIZE + n;
        float c0 = acc[mf][nf][half * 2 + 0] + b[n];
        float c1 = acc[mf][nf][half * 2 + 1] + b[n + 1];
        bool vis = (n < V_SIZE);  // n even, V even -> pair stays inside block
        float l0 = (vis && n != m) ? REC_F : 1.0f;
        float l1 = (vis && (n + 1) != m) ? REC_F : 1.0f;
        float u0 = l0 * c0;
        float u1 = l1 * c1;
        if (vis) {
          u0 = fmaf(1.f - l0, Xr[n], u0);
          u1 = fmaf(1.f - l1, Xr[n + 1], u1);
        }
        __half2 hv;
        hv.x = __float2half(fast_tanh(u0));
        hv.y = __float2half(fast_tanh(u1));
        *reinterpret_cast<__half2*>(O + idx) = hv;
      }
}

// -------- final step (t=63): output needs only diag(U[:, :V]) --------
// lam[i,i] = 1  =>  diag[i] = dot(R_63[i,:], W[i,:]) + b[i]   (fp32 W, exact)
__global__ void __launch_bounds__(256, 1)
diag_kernel(const float* __restrict__ W, const float* __restrict__ b,
            float* __restrict__ diag) {
  const int lane = threadIdx.x & 31;
  const int row = blockIdx.x * 8 + (threadIdx.x >> 5);  // one warp per row
  if (row >= V_SIZE) return;

  const __half* __restrict__ r = g_R[1] + (size_t)row * F_SIZE;
  const float* __restrict__ w = W + (size_t)row * F_SIZE;

  float acc = 0.f;
#pragma unroll
  for (int k0 = lane * 4; k0 < F_SIZE; k0 += 128) {
    __half2 rv01 = *reinterpret_cast<const __half2*>(r + k0);
    __half2 rv23 = *reinterpret_cast<const __half2*>(r + k0 + 2);
    float4 wv = *reinterpret_cast<const float4*>(w + k0);
    float2 f01 = __half22float2(rv01);
    float2 f23 = __half22float2(rv23);
    acc = fmaf(f01.x, wv.x, acc);
    acc = fmaf(f01.y, wv.y, acc);
    acc = fmaf(f23.x, wv.z, acc);
    acc = fmaf(f23.y, wv.w, acc);
  }
#pragma unroll
  for (int off = 16; off > 0; off >>= 1)
    acc += __shfl_xor_sync(0xFFFFFFFFu, acc, off);
  if (lane == 0) diag[row] = acc + b[row];
}

// ---------------- host launch ----------------
extern "C" void kernel_launch(void* const* d_in, const int* in_sizes, int n_in,
                              void* d_out, int out_size) {
  const float* X = (const float*)d_in[0];    // [T, V]
  const float* W = (const float*)d_in[1];    // [F, F]
  const float* b = (const float*)d_in[2];    // [F]
  const float* lam = (const float*)d_in[3];  // [V, F]
  float* out = (float*)d_out;                // [V]

  cudaFuncSetAttribute(gemm_step_kernel,
                       cudaFuncAttributeMaxDynamicSharedMemorySize, SMEM_BYTES);

  split_w_kernel<<<2048, 512>>>(W);
  step0_kernel<<<2048, 512>>>(X, b, lam);

  dim3 grid(F_SIZE / BN, V_SIZE / BM);  // (32, 8) = 256 CTAs, 2 per SM
  for (int t = 1; t < T_STEPS - 1; ++t) {  // t = 1..62
    gemm_step_kernel<<<grid, NTHREADS, SMEM_BYTES>>>(t, X, b);
  }
  diag_kernel<<<V_SIZE / 8, 256>>>(W, b, out);  // t = 63, diag only
}

// round 16
// speedup vs baseline: 1.3172x; 1.3172x over previous
#include <cuda_runtime.h>
#include <cuda_fp16.h>
#include <cstdint>
#include <cstddef>

// ---------------- problem constants ----------------
#define V_SIZE 1024
#define H_SIZE 2048
#define F_SIZE 3072
#define T_STEPS 64
#define REC_F 0.8f

// ---------------- GEMM tiling (dual-CTA-per-SM, R12 config) ----------------
#define BM 128
#define BN 96
#define BK 64
#define KCHUNKS (F_SIZE / BK)   // 48
#define NTHREADS 128            // 4 warps: 2(M) x 2(N), warp tile 64x48
#define NSTAGES 2

// SMEM per stage: A(16K) Bh(12K) Bl(12K) = 40K
#define OFF_A  0
#define OFF_BH 16384
#define OFF_BL 28672
#define STAGE_BYTES 40960
// layout: [align slack 1K][hdr 1K: mbarriers][2 stages] = 84KB -> 2 CTAs/SM
#define SMEM_BYTES (1024 + 1024 + NSTAGES * STAGE_BYTES)

// ---------------- device scratch ----------------
// Wh = fp16(W); Wl = fp16((W - Wh) * 64)  (scaled into fp16-normal range)
__device__ __half g_Wh[(size_t)F_SIZE * F_SIZE];
__device__ __half g_Wl[(size_t)F_SIZE * F_SIZE];
__device__ __half g_R[2][(size_t)V_SIZE * F_SIZE];

__device__ __forceinline__ uint32_t swz(uint32_t o) { return o ^ ((o >> 3) & 0x70u); }

#define LDM4(R_, A_)                                                              \
  asm volatile("ldmatrix.sync.aligned.m8n8.x4.shared.b16 {%0,%1,%2,%3}, [%4];"    \
               : "=r"((R_)[0]), "=r"((R_)[1]), "=r"((R_)[2]), "=r"((R_)[3])       \
               : "r"(A_))

#define MMA16816(C_, A_, B0_, B1_)                                                \
  asm volatile("mma.sync.aligned.m16n8k16.row.col.f32.f16.f16.f32 "               \
               "{%0,%1,%2,%3},{%4,%5,%6,%7},{%8,%9},{%0,%1,%2,%3};"               \
               : "+f"((C_)[0]), "+f"((C_)[1]), "+f"((C_)[2]), "+f"((C_)[3])       \
               : "r"((A_)[0]), "r"((A_)[1]), "r"((A_)[2]), "r"((A_)[3]),          \
                 "r"(B0_), "r"(B1_))

#define CP16(SO_, G_)                                                             \
  asm volatile("cp.async.cg.shared.global [%0], [%1], 16;" :: "r"(SO_), "l"(G_))

// .noinc: one arrival per thread when that thread's prior cp.asyncs complete.
#define CP_ASYNC_MBAR_ARRIVE_NOINC(mbar)                                          \
  asm volatile("cp.async.mbarrier.arrive.noinc.shared.b64 [%0];"                  \
               :: "r"((uint32_t)(mbar)) : "memory")

#define MBARRIER_INIT(mbar, count)                                                \
  asm volatile("mbarrier.init.shared.b64 [%0], %1;"                               \
               :: "r"((uint32_t)(mbar)), "r"((uint32_t)(count)) : "memory")
#define MBARRIER_ARRIVE(mbar)                                                     \
  asm volatile("mbarrier.arrive.shared.b64 _, [%0];"                              \
               :: "r"((uint32_t)(mbar)) : "memory")

__device__ __forceinline__ void mbar_wait_parity(uint32_t mbar, uint32_t parity) {
  uint32_t done;
  asm volatile("{\n\t.reg .pred p;\n\t"
               "mbarrier.try_wait.parity.acquire.cta.shared::cta.b64 p, [%1], %2;\n\t"
               "selp.b32 %0, 1, 0, p;\n\t}"
               : "=r"(done) : "r"(mbar), "r"(parity) : "memory");
  if (!done) {
    asm volatile("{\n\t.reg .pred P1;\n\t"
                 "WAIT_LOOP_%=:\n\t"
                 "mbarrier.try_wait.parity.acquire.cta.shared::cta.b64 P1, [%0], %1, 0x989680;\n\t"
                 "@P1 bra.uni WAIT_DONE_%=;\n\t"
                 "bra.uni WAIT_LOOP_%=;\n\t"
                 "WAIT_DONE_%=:\n\t}"
                 :: "r"(mbar), "r"(parity) : "memory");
  }
}

#define HALF2_POW2_M6 0x24002400u
__device__ __forceinline__ uint32_t hmul2_scale(uint32_t a) {
  uint32_t r;
  asm volatile("mul.f16x2 %0, %1, %2;" : "=r"(r) : "r"(a), "r"(HALF2_POW2_M6));
  return r;
}

__device__ __forceinline__ float fast_tanh(float x) {
  float e = __expf(2.f * x);
  return 1.f - __fdividef(2.f, e + 1.f);
}

// -------- W split (vectorized x4): fp32 -> fp16 hi + fp16 lo (lo * 2^6) -----
__global__ void split_w_kernel(const float* __restrict__ W) {
  const int n4 = F_SIZE * F_SIZE / 4;
  for (int i4 = blockIdx.x * blockDim.x + threadIdx.x; i4 < n4;
       i4 += gridDim.x * blockDim.x) {
    const float4 w4 = *reinterpret_cast<const float4*>(W + (size_t)i4 * 4);
    float wv[4] = {w4.x, w4.y, w4.z, w4.w};
    __half hh[4];
    __half hl[4];
#pragma unroll
    for (int j = 0; j < 4; ++j) {
      hh[j] = __float2half(wv[j]);
      hl[j] = __float2half((wv[j] - __half2float(hh[j])) * 64.f);
    }
    *reinterpret_cast<uint2*>(g_Wh + (size_t)i4 * 4) =
        *reinterpret_cast<uint2*>(hh);
    *reinterpret_cast<uint2*>(g_Wl + (size_t)i4 * 4) =
        *reinterpret_cast<uint2*>(hl);
  }
}

// -------- step 0 (vectorized x4, lam from indices): R_0 = 0, epilogue-only --
__global__ void step0_kernel(const float* __restrict__ X,
                             const float* __restrict__ b) {
  const int n4 = V_SIZE * F_SIZE / 4;
  for (int i4 = blockIdx.x * blockDim.x + threadIdx.x; i4 < n4;
       i4 += gridDim.x * blockDim.x) {
    const int i = i4 * 4;
    const int row = i / F_SIZE;
    const int c = i % F_SIZE;           // c..c+3 share the row (4 | F_SIZE)
    const float4 b4 = *reinterpret_cast<const float4*>(b + c);
    float bv[4] = {b4.x, b4.y, b4.z, b4.w};
    const bool vis = (c < V_SIZE);      // 4 | V_SIZE -> whole quad same side
    float xv[4] = {0.f, 0.f, 0.f, 0.f};
    if (vis) {
      const float4 x4 = *reinterpret_cast<const float4*>(X + c);  // x_0
      xv[0] = x4.x; xv[1] = x4.y; xv[2] = x4.z; xv[3] = x4.w;
    }
    __half hr[4];
#pragma unroll
    for (int j = 0; j < 4; ++j) {
      float l = (vis && (c + j) != row) ? REC_F : 1.0f;
      float u = l * bv[j];
      if (vis) u += (1.f - l) * xv[j];
      hr[j] = __float2half(tanhf(u));
    }
    *reinterpret_cast<uint2*>(g_R[1] + (size_t)i) =
        *reinterpret_cast<uint2*>(hr);
  }
}

// -------- steps 1..62: C = R @ W^T (fp16 2-pass) + fused epilogue (R12) -----
__global__ void __launch_bounds__(NTHREADS, 2)
gemm_step_kernel(int t, const float* __restrict__ X, const float* __restrict__ b) {
  extern __shared__ unsigned char smem_raw[];
  uint32_t sbase = (uint32_t)__cvta_generic_to_shared(smem_raw);
  sbase = (sbase + 1023u) & ~1023u;  // SW128 swizzle wants 1KB alignment
  const uint32_t hdr = sbase;        // full[s]=hdr+s*8, empty[s]=hdr+64+s*8
  const uint32_t tiles = sbase + 1024;

  const __half* __restrict__ A = g_R[t & 1];
  __half* __restrict__ O = g_R[(t + 1) & 1];
  const float* __restrict__ Xr = X + (size_t)t * V_SIZE;

  const int tid = threadIdx.x;
  const int lane = tid & 31;
  const int wid = tid >> 5;
  const int wm = (wid >> 1) * 64;      // 0 / 64
  const int wn = (wid & 1) * 48;       // 0 / 48
  const int m0 = blockIdx.y * BM;
  const int n0 = blockIdx.x * BN;

  const __half* __restrict__ srcA  = A + (size_t)m0 * F_SIZE;
  const __half* __restrict__ srcBh = g_Wh + (size_t)n0 * F_SIZE;
  const __half* __restrict__ srcBl = g_Wl + (size_t)n0 * F_SIZE;

  if (tid == 0) {
#pragma unroll
    for (int s = 0; s < NSTAGES; ++s) {
      MBARRIER_INIT(hdr + s * 8, NTHREADS);       // full[s]
      MBARRIER_INIT(hdr + 64 + s * 8, NTHREADS);  // empty[s]
    }
  }
  __syncthreads();

  float acc[4][6][4];
#pragma unroll
  for (int i = 0; i < 4; ++i)
#pragma unroll
    for (int j = 0; j < 6; ++j)
#pragma unroll
      for (int k = 0; k < 4; ++k) acc[i][j][k] = 0.f;

  // --- async tile loader: 2560 x 16B chunks (A:1024, Bh:768, Bl:768) ---
  auto load_chunk = [&](int stage, int kc) {
    const uint32_t sb = tiles + (uint32_t)stage * STAGE_BYTES;
    const int koff = kc * BK;
#pragma unroll
    for (int it = 0; it < 20; ++it) {
      int i = tid + it * NTHREADS;
      const __half* gb;
      uint32_t stile;
      int j;
      if (i < 1024) {                       // A tile (128 rows)
        j = i;
        gb = srcA;
        stile = OFF_A;
      } else if (i < 1792) {                // Bh tile (96 rows)
        j = i - 1024;
        gb = srcBh;
        stile = OFF_BH;
      } else {                              // Bl tile (96 rows)
        j = i - 1792;
        gb = srcBl;
        stile = OFF_BL;
      }
      int r = j >> 3, c = j & 7;
      const void* g = gb + (size_t)r * F_SIZE + koff + c * 8;
      uint32_t so = sb + stile + swz((uint32_t)(r * 128 + c * 16));
      CP16(so, g);
    }
    CP_ASYNC_MBAR_ARRIVE_NOINC(hdr + stage * 8);  // full[stage]
  };

  // --- warp compute (64x48 tile); arrives on empty[stage] after last LDSM ---
  auto compute = [&](int stage) {
    const uint32_t sb = tiles + (uint32_t)stage * STAGE_BYTES;
    const uint32_t aT = sb + OFF_A;
    const uint32_t bH = sb + OFF_BH;
    const uint32_t bL = sb + OFF_BL;
#pragma unroll
    for (int ks = 0; ks < 4; ++ks) {
      uint32_t ah[4][4], as[4][4], bh[3][4], bl[3][4];
#pragma unroll
      for (int mf = 0; mf < 4; ++mf) {
        uint32_t off = swz((uint32_t)((wm + mf * 16 + (lane & 15)) * 128 +
                                      (ks * 16 + ((lane >> 4) << 3)) * 2));
        LDM4(ah[mf], aT + off);
#pragma unroll
        for (int q = 0; q < 4; ++q) as[mf][q] = hmul2_scale(ah[mf][q]);
      }
#pragma unroll
      for (int nf2 = 0; nf2 < 3; ++nf2) {
        uint32_t off = swz((uint32_t)(
            (wn + nf2 * 16 + (lane & 7) + (((lane >> 4) & 1) << 3)) * 128 +
            (ks * 16 + ((lane >> 3) & 1) * 8) * 2));
        LDM4(bh[nf2], bH + off);
        LDM4(bl[nf2], bL + off);
      }
      if (ks == 3) {
        // all of this thread's reads from `stage` done (fragments in regs)
        MBARRIER_ARRIVE(hdr + 64 + stage * 8);  // empty[stage]
      }
#pragma unroll
      for (int mf = 0; mf < 4; ++mf)
#pragma unroll
        for (int nf = 0; nf < 6; ++nf) {
          float* c = acc[mf][nf];
          uint32_t b0h = bh[nf >> 1][(nf & 1) * 2];
          uint32_t b1h = bh[nf >> 1][(nf & 1) * 2 + 1];
          uint32_t b0l = bl[nf >> 1][(nf & 1) * 2];
          uint32_t b1l = bl[nf >> 1][(nf & 1) * 2 + 1];
          MMA16816(c, ah[mf], b0h, b1h);  // Rh * Wh
          MMA16816(c, as[mf], b0l, b1l);  // (Rh*2^-6) * (Wl*2^6) = Rh * Wl
        }
    }
  };

  // --- mainloop: 2-stage ring; compute-then-load order (2-stage safe) ---
  // chunk c -> stage c&1, use j=c>>1; full parity j&1; empty parity j&1.
  load_chunk(0, 0);
  load_chunk(1, 1);
  for (int kc = 0; kc < KCHUNKS; ++kc) {
    const int s = kc & 1;
    const uint32_t j = (uint32_t)(kc >> 1);
    mbar_wait_parity(hdr + s * 8, j & 1);      // full[s] for chunk kc
    compute(s);                                 // empty-arrive inside (ks==3)
    if (kc + 2 < KCHUNKS) {
      mbar_wait_parity(hdr + 64 + s * 8, j & 1);  // all warps done reading s
      load_chunk(s, kc + 2);
    }
  }

  // --- fused epilogue: lam from indices; U = lam*(C+b) + (1-lam)*x_t; tanh ---
#pragma unroll
  for (int mf = 0; mf < 4; ++mf)
#pragma unroll
    for (int nf = 0; nf < 6; ++nf)
#pragma unroll
      for (int half = 0; half < 2; ++half) {
        int m = m0 + wm + mf * 16 + (lane >> 2) + half * 8;
        int n = n0 + wn + nf * 8 + 2 * (lane & 3);
        size_t idx = (size_t)m * F_SIZE + n;
        float c0 = acc[mf][nf][half * 2 + 0] + b[n];
        float c1 = acc[mf][nf][half * 2 + 1] + b[n + 1];
        bool vis = (n < V_SIZE);  // n even, V even -> pair stays inside block
        float l0 = (vis && n != m) ? REC_F : 1.0f;
        float l1 = (vis && (n + 1) != m) ? REC_F : 1.0f;
        float u0 = l0 * c0;
        float u1 = l1 * c1;
        if (vis) {
          u0 = fmaf(1.f - l0, Xr[n], u0);
          u1 = fmaf(1.f - l1, Xr[n + 1], u1);
        }
        __half2 hv;
        hv.x = __float2half(fast_tanh(u0));
        hv.y = __float2half(fast_tanh(u1));
        *reinterpret_cast<__half2*>(O + idx) = hv;
      }
}

// -------- final step (t=63): output needs only diag(U[:, :V]) --------
// lam[i,i] = 1  =>  diag[i] = dot(R_63[i,:], W[i,:]) + b[i]   (fp32 W, exact)
__global__ void __launch_bounds__(256, 1)
diag_kernel(const float* __restrict__ W, const float* __restrict__ b,
            float* __restrict__ diag) {
  const int lane = threadIdx.x & 31;
  const int row = blockIdx.x * 8 + (threadIdx.x >> 5);  // one warp per row
  if (row >= V_SIZE) return;

  const __half* __restrict__ r = g_R[1] + (size_t)row * F_SIZE;
  const float* __restrict__ w = W + (size_t)row * F_SIZE;

  float acc = 0.f;
#pragma unroll
  for (int k0 = lane * 4; k0 < F_SIZE; k0 += 128) {
    __half2 rv01 = *reinterpret_cast<const __half2*>(r + k0);
    __half2 rv23 = *reinterpret_cast<const __half2*>(r + k0 + 2);
    float4 wv = *reinterpret_cast<const float4*>(w + k0);
    float2 f01 = __half22float2(rv01);
    float2 f23 = __half22float2(rv23);
    acc = fmaf(f01.x, wv.x, acc);
    acc = fmaf(f01.y, wv.y, acc);
    acc = fmaf(f23.x, wv.z, acc);
    acc = fmaf(f23.y, wv.w, acc);
  }
#pragma unroll
  for (int off = 16; off > 0; off >>= 1)
    acc += __shfl_xor_sync(0xFFFFFFFFu, acc, off);
  if (lane == 0) diag[row] = acc + b[row];
}

// ---------------- host launch ----------------
extern "C" void kernel_launch(void* const* d_in, const int* in_sizes, int n_in,
                              void* d_out, int out_size) {
  const float* X = (const float*)d_in[0];    // [T, V]
  const float* W = (const float*)d_in[1];    // [F, F]
  const float* b = (const float*)d_in[2];    // [F]
  float* out = (float*)d_out;                // [V]

  cudaFuncSetAttribute(gemm_step_kernel,
                       cudaFuncAttributeMaxDynamicSharedMemorySize, SMEM_BYTES);

  split_w_kernel<<<2048, 512>>>(W);
  step0_kernel<<<1024, 512>>>(X, b);

  dim3 grid(F_SIZE / BN, V_SIZE / BM);  // (32, 8) = 256 CTAs, 2 per SM
  for (int t = 1; t < T_STEPS - 1; ++t) {  // t = 1..62
    gemm_step_kernel<<<grid, NTHREADS, SMEM_BYTES>>>(t, X, b);
  }
  diag_kernel<<<V_SIZE / 8, 256>>>(W, b, out);  // t = 63, diag only
}

// round 17
// speedup vs baseline: 2.0562x; 1.5610x over previous
#include <cuda_runtime.h>
#include <cuda_fp16.h>
#include <cstdint>
#include <cstddef>

// ---------------- problem constants ----------------
#define V_SIZE 1024
#define H_SIZE 2048
#define F_SIZE 3072
#define T_STEPS 64
#define REC_F 0.8f

// ---------------- GEMM tiling (dual-CTA-per-SM config) ----------------
#define BM 128
#define BN 96
#define BK 64
#define KCHUNKS (F_SIZE / BK)   // 48
#define NTHREADS 128            // 4 warps: 2(M) x 2(N), warp tile 64x48
#define NSTAGES 2

// SMEM per stage: A(16K) Bh(12K) Bl(12K) = 40K
#define OFF_A  0
#define OFF_BH 16384
#define OFF_BL 28672
#define STAGE_BYTES 40960
// layout: [align slack 1K][hdr 1K: mbarriers][2 stages] = 84KB -> 2 CTAs/SM
#define SMEM_BYTES (1024 + 1024 + NSTAGES * STAGE_BYTES)

// ---------------- device scratch ----------------
// Wh = fp16(W); Wl = fp16((W - Wh) * 64)  (scaled into fp16-normal range)
__device__ __half g_Wh[(size_t)F_SIZE * F_SIZE];
__device__ __half g_Wl[(size_t)F_SIZE * F_SIZE];
__device__ __half g_R[2][(size_t)V_SIZE * F_SIZE];

__device__ __forceinline__ uint32_t swz(uint32_t o) { return o ^ ((o >> 3) & 0x70u); }

#define LDM4(R_, A_)                                                              \
  asm volatile("ldmatrix.sync.aligned.m8n8.x4.shared.b16 {%0,%1,%2,%3}, [%4];"    \
               : "=r"((R_)[0]), "=r"((R_)[1]), "=r"((R_)[2]), "=r"((R_)[3])       \
               : "r"(A_))

#define MMA16816(C_, A_, B0_, B1_)                                                \
  asm volatile("mma.sync.aligned.m16n8k16.row.col.f32.f16.f16.f32 "               \
               "{%0,%1,%2,%3},{%4,%5,%6,%7},{%8,%9},{%0,%1,%2,%3};"               \
               : "+f"((C_)[0]), "+f"((C_)[1]), "+f"((C_)[2]), "+f"((C_)[3])       \
               : "r"((A_)[0]), "r"((A_)[1]), "r"((A_)[2]), "r"((A_)[3]),          \
                 "r"(B0_), "r"(B1_))

#define CP16(SO_, G_)                                                             \
  asm volatile("cp.async.cg.shared.global [%0], [%1], 16;" :: "r"(SO_), "l"(G_))

// .noinc: one arrival per thread when that thread's prior cp.asyncs complete.
#define CP_ASYNC_MBAR_ARRIVE_NOINC(mbar)                                          \
  asm volatile("cp.async.mbarrier.arrive.noinc.shared.b64 [%0];"                  \
               :: "r"((uint32_t)(mbar)) : "memory")

#define MBARRIER_INIT(mbar, count)                                                \
  asm volatile("mbarrier.init.shared.b64 [%0], %1;"                               \
               :: "r"((uint32_t)(mbar)), "r"((uint32_t)(count)) : "memory")
#define MBARRIER_ARRIVE(mbar)                                                     \
  asm volatile("mbarrier.arrive.shared.b64 _, [%0];"                              \
               :: "r"((uint32_t)(mbar)) : "memory")

__device__ __forceinline__ void mbar_wait_parity(uint32_t mbar, uint32_t parity) {
  uint32_t done;
  asm volatile("{\n\t.reg .pred p;\n\t"
               "mbarrier.try_wait.parity.acquire.cta.shared::cta.b64 p, [%1], %2;\n\t"
               "selp.b32 %0, 1, 0, p;\n\t}"
               : "=r"(done) : "r"(mbar), "r"(parity) : "memory");
  if (!done) {
    asm volatile("{\n\t.reg .pred P1;\n\t"
                 "WAIT_LOOP_%=:\n\t"
                 "mbarrier.try_wait.parity.acquire.cta.shared::cta.b64 P1, [%0], %1, 0x989680;\n\t"
                 "@P1 bra.uni WAIT_DONE_%=;\n\t"
                 "bra.uni WAIT_LOOP_%=;\n\t"
                 "WAIT_DONE_%=:\n\t}"
                 :: "r"(mbar), "r"(parity) : "memory");
  }
}

#define HALF2_POW2_M6 0x24002400u
__device__ __forceinline__ uint32_t hmul2_scale(uint32_t a) {
  uint32_t r;
  asm volatile("mul.f16x2 %0, %1, %2;" : "=r"(r) : "r"(a), "r"(HALF2_POW2_M6));
  return r;
}

__device__ __forceinline__ float fast_tanh(float x) {
  float e = __expf(2.f * x);
  return 1.f - __fdividef(2.f, e + 1.f);
}

// -------- W split: fp32 -> fp16 hi + fp16 lo (lo pre-scaled by 2^6) --------
__global__ void split_w_kernel(const float* __restrict__ W) {
  const int n = F_SIZE * F_SIZE;
  for (int i = blockIdx.x * blockDim.x + threadIdx.x; i < n;
       i += gridDim.x * blockDim.x) {
    float w = W[i];
    __half h = __float2half(w);
    g_Wh[i] = h;
    g_Wl[i] = __float2half((w - __half2float(h)) * 64.f);
  }
}

// -------- step 0: R_0 = 0, epilogue-only --------
__global__ void step0_kernel(const float* __restrict__ X,
                             const float* __restrict__ b,
                             const float* __restrict__ lam) {
  const int n = V_SIZE * F_SIZE;
  for (int i = blockIdx.x * blockDim.x + threadIdx.x; i < n;
       i += gridDim.x * blockDim.x) {
    int c = i % F_SIZE;
    float l = lam[i];
    float u = l * b[c];
    if (c < V_SIZE) u += (1.f - l) * X[c];  // x_0
    g_R[1][i] = __float2half(tanhf(u));
  }
}

// -------- steps 1..62: C = R @ W^T (fp16 2-pass) + fused epilogue --------
__global__ void __launch_bounds__(NTHREADS, 2)
gemm_step_kernel(int t, const float* __restrict__ X, const float* __restrict__ b) {
  extern __shared__ unsigned char smem_raw[];
  uint32_t sbase = (uint32_t)__cvta_generic_to_shared(smem_raw);
  sbase = (sbase + 1023u) & ~1023u;  // SW128 swizzle wants 1KB alignment
  const uint32_t hdr = sbase;        // full[s]=hdr+s*8, empty[s]=hdr+64+s*8
  const uint32_t tiles = sbase + 1024;

  const __half* __restrict__ A = g_R[t & 1];
  __half* __restrict__ O = g_R[(t + 1) & 1];
  const float* __restrict__ Xr = X + (size_t)t * V_SIZE;

  const int tid = threadIdx.x;
  const int lane = tid & 31;
  const int wid = tid >> 5;
  const int wm = (wid >> 1) * 64;      // 0 / 64
  const int wn = (wid & 1) * 48;       // 0 / 48
  const int m0 = blockIdx.y * BM;
  const int n0 = blockIdx.x * BN;

  const __half* __restrict__ srcA  = A + (size_t)m0 * F_SIZE;
  const __half* __restrict__ srcBh = g_Wh + (size_t)n0 * F_SIZE;
  const __half* __restrict__ srcBl = g_Wl + (size_t)n0 * F_SIZE;

  if (tid == 0) {
#pragma unroll
    for (int s = 0; s < NSTAGES; ++s) {
      MBARRIER_INIT(hdr + s * 8, NTHREADS);       // full[s]
      MBARRIER_INIT(hdr + 64 + s * 8, NTHREADS);  // empty[s]
    }
  }
  __syncthreads();

  float acc[4][6][4];
#pragma unroll
  for (int i = 0; i < 4; ++i)
#pragma unroll
    for (int j = 0; j < 6; ++j)
#pragma unroll
      for (int k = 0; k < 4; ++k) acc[i][j][k] = 0.f;

  // --- async tile loader: 2560 x 16B chunks (A:1024, Bh:768, Bl:768) ---
  auto load_chunk = [&](int stage, int kc) {
    const uint32_t sb = tiles + (uint32_t)stage * STAGE_BYTES;
    const int koff = kc * BK;
#pragma unroll
    for (int it = 0; it < 20; ++it) {
      int i = tid + it * NTHREADS;
      const __half* gb;
      uint32_t stile;
      int j;
      if (i < 1024) {                       // A tile (128 rows)
        j = i;
        gb = srcA;
        stile = OFF_A;
      } else if (i < 1792) {                // Bh tile (96 rows)
        j = i - 1024;
        gb = srcBh;
        stile = OFF_BH;
      } else {                              // Bl tile (96 rows)
        j = i - 1792;
        gb = srcBl;
        stile = OFF_BL;
      }
      int r = j >> 3, c = j & 7;
      const void* g = gb + (size_t)r * F_SIZE + koff + c * 8;
      uint32_t so = sb + stile + swz((uint32_t)(r * 128 + c * 16));
      CP16(so, g);
    }
    CP_ASYNC_MBAR_ARRIVE_NOINC(hdr + stage * 8);  // full[stage]
  };

  // --- warp compute (64x48 tile); arrives on empty[stage] after last LDSM ---
  auto compute = [&](int stage) {
    const uint32_t sb = tiles + (uint32_t)stage * STAGE_BYTES;
    const uint32_t aT = sb + OFF_A;
    const uint32_t bH = sb + OFF_BH;
    const uint32_t bL = sb + OFF_BL;
#pragma unroll
    for (int ks = 0; ks < 4; ++ks) {
      uint32_t ah[4][4], as[4][4], bh[3][4], bl[3][4];
#pragma unroll
      for (int mf = 0; mf < 4; ++mf) {
        uint32_t off = swz((uint32_t)((wm + mf * 16 + (lane & 15)) * 128 +
                                      (ks * 16 + ((lane >> 4) << 3)) * 2));
        LDM4(ah[mf], aT + off);
#pragma unroll
        for (int q = 0; q < 4; ++q) as[mf][q] = hmul2_scale(ah[mf][q]);
      }
#pragma unroll
      for (int nf2 = 0; nf2 < 3; ++nf2) {
        uint32_t off = swz((uint32_t)(
            (wn + nf2 * 16 + (lane & 7) + (((lane >> 4) & 1) << 3)) * 128 +
            (ks * 16 + ((lane >> 3) & 1) * 8) * 2));
        LDM4(bh[nf2], bH + off);
        LDM4(bl[nf2], bL + off);
      }
      if (ks == 3) {
        // all of this thread's reads from `stage` done (fragments in regs)
        MBARRIER_ARRIVE(hdr + 64 + stage * 8);  // empty[stage]
      }
#pragma unroll
      for (int mf = 0; mf < 4; ++mf)
#pragma unroll
        for (int nf = 0; nf < 6; ++nf) {
          float* c = acc[mf][nf];
          uint32_t b0h = bh[nf >> 1][(nf & 1) * 2];
          uint32_t b1h = bh[nf >> 1][(nf & 1) * 2 + 1];
          uint32_t b0l = bl[nf >> 1][(nf & 1) * 2];
          uint32_t b1l = bl[nf >> 1][(nf & 1) * 2 + 1];
          MMA16816(c, ah[mf], b0h, b1h);  // Rh * Wh
          MMA16816(c, as[mf], b0l, b1l);  // (Rh*2^-6) * (Wl*2^6) = Rh * Wl
        }
    }
  };

  // --- mainloop: 2-stage ring; compute-then-load order (2-stage safe) ---
  // chunk c -> stage c&1, use j=c>>1; full parity j&1; empty parity j&1.
  load_chunk(0, 0);
  load_chunk(1, 1);
  for (int kc = 0; kc < KCHUNKS; ++kc) {
    const int s = kc & 1;
    const uint32_t j = (uint32_t)(kc >> 1);
    mbar_wait_parity(hdr + s * 8, j & 1);      // full[s] for chunk kc
    compute(s);                                 // empty-arrive inside (ks==3)
    if (kc + 2 < KCHUNKS) {
      mbar_wait_parity(hdr + 64 + s * 8, j & 1);  // all warps done reading s
      load_chunk(s, kc + 2);
    }
  }

  // --- fused epilogue: lam from indices; U = lam*(C+b) + (1-lam)*x_t; tanh ---
#pragma unroll
  for (int mf = 0; mf < 4; ++mf)
#pragma unroll
    for (int nf = 0; nf < 6; ++nf)
#pragma unroll
      for (int half = 0; half < 2; ++half) {
        int m = m0 + wm + mf * 16 + (lane >> 2) + half * 8;
        int n = n0 + wn + nf * 8 + 2 * (lane & 3);
        size_t idx = (size_t)m * F_SIZE + n;
        float c0 = acc[mf][nf][half * 2 + 0] + b[n];
        float c1 = acc[mf][nf][half * 2 + 1] + b[n + 1];
        bool vis = (n < V_SIZE);  // n even, V even -> pair stays inside block
        float l0 = (vis && n != m) ? REC_F : 1.0f;
        float l1 = (vis && (n + 1) != m) ? REC_F : 1.0f;
        float u0 = l0 * c0;
        float u1 = l1 * c1;
        if (vis) {
          u0 = fmaf(1.f - l0, Xr[n], u0);
          u1 = fmaf(1.f - l1, Xr[n + 1], u1);
        }
        __half2 hv;
        hv.x = __float2half(fast_tanh(u0));
        hv.y = __float2half(fast_tanh(u1));
        *reinterpret_cast<__half2*>(O + idx) = hv;
      }
}

// -------- final step (t=63): output needs only diag(U[:, :V]) --------
// lam[i,i] = 1  =>  diag[i] = dot(R_63[i,:], W[i,:]) + b[i]   (fp32 W, exact)
__global__ void __launch_bounds__(256, 1)
diag_kernel(const float* __restrict__ W, const float* __restrict__ b,
            float* __restrict__ diag) {
  const int lane = threadIdx.x & 31;
  const int row = blockIdx.x * 8 + (threadIdx.x >> 5);  // one warp per row
  if (row >= V_SIZE) return;

  const __half* __restrict__ r = g_R[1] + (size_t)row * F_SIZE;
  const float* __restrict__ w = W + (size_t)row * F_SIZE;

  float acc = 0.f;
#pragma unroll
  for (int k0 = lane * 4; k0 < F_SIZE; k0 += 128) {
    __half2 rv01 = *reinterpret_cast<const __half2*>(r + k0);
    __half2 rv23 = *reinterpret_cast<const __half2*>(r + k0 + 2);
    float4 wv = *reinterpret_cast<const float4*>(w + k0);
    float2 f01 = __half22float2(rv01);
    float2 f23 = __half22float2(rv23);
    acc = fmaf(f01.x, wv.x, acc);
    acc = fmaf(f01.y, wv.y, acc);
    acc = fmaf(f23.x, wv.z, acc);
    acc = fmaf(f23.y, wv.w, acc);
  }
#pragma unroll
  for (int off = 16; off > 0; off >>= 1)
    acc += __shfl_xor_sync(0xFFFFFFFFu, acc, off);
  if (lane == 0) diag[row] = acc + b[row];
}

// ---------------- host launch ----------------
extern "C" void kernel_launch(void* const* d_in, const int* in_sizes, int n_in,
                              void* d_out, int out_size) {
  const float* X = (const float*)d_in[0];    // [T, V]
  const float* W = (const float*)d_in[1];    // [F, F]
  const float* b = (const float*)d_in[2];    // [F]
  const float* lam = (const float*)d_in[3];  // [V, F]
  float* out = (float*)d_out;                // [V]

  cudaFuncSetAttribute(gemm_step_kernel,
                       cudaFuncAttributeMaxDynamicSharedMemorySize, SMEM_BYTES);

  split_w_kernel<<<2048, 512>>>(W);
  step0_kernel<<<2048, 512>>>(X, b, lam);

  dim3 grid(F_SIZE / BN, V_SIZE / BM);  // (32, 8) = 256 CTAs, 2 per SM
  for (int t = 1; t < T_STEPS - 1; ++t) {  // t = 1..62
    gemm_step_kernel<<<grid, NTHREADS, SMEM_BYTES>>>(t, X, b);
  }
  diag_kernel<<<V_SIZE / 8, 256>>>(W, b, out);  // t = 63, diag only
}